// round 3
// baseline (speedup 1.0000x reference)
#include <cuda_runtime.h>
#include <math.h>

#define VOLD 256
#define H_ 200
#define W_ 200

// Transposed volume: g_volT[z][y][x], x contiguous. 64 MB static device scratch.
__device__ float g_volT[VOLD * VOLD * VOLD];

// ---------------------------------------------------------------------------
// Kernel 1: x<->z transpose so that the axis that varies across adjacent
// pixels (x) becomes the contiguous axis. Classic 32x32 smem tile per y-slice.
// ---------------------------------------------------------------------------
__global__ void __launch_bounds__(256) transpose_xz(const float* __restrict__ vol) {
    __shared__ float tile[32][33];
    const int tx = threadIdx.x;           // 0..31
    const int ty = threadIdx.y;           // 0..7
    const int xB = blockIdx.x * 32;
    const int zB = blockIdx.y * 32;
    const int y  = blockIdx.z;

    // Read: vol[x][y][z], z contiguous -> lanes sweep z (coalesced)
#pragma unroll
    for (int i = 0; i < 32; i += 8) {
        tile[ty + i][tx] = vol[((xB + ty + i) * VOLD + y) * VOLD + (zB + tx)];
    }
    __syncthreads();
    // Write: g_volT[z][y][x], x contiguous -> lanes sweep x (coalesced)
#pragma unroll
    for (int i = 0; i < 32; i += 8) {
        g_volT[((zB + ty + i) * VOLD + y) * VOLD + (xB + tx)] = tile[tx][ty + i];
    }
}

// Trilinear corner fetch with zero padding (map_coordinates mode='constant').
__device__ __forceinline__ float fetchT(int x, int y, int z) {
    if ((unsigned)x < (unsigned)VOLD && (unsigned)y < (unsigned)VOLD &&
        (unsigned)z < (unsigned)VOLD) {
        return __ldg(&g_volT[(z * VOLD + y) * VOLD + x]);
    }
    return 0.0f;
}

// ---------------------------------------------------------------------------
// Kernel 2: DRR ray marching.
//   block = 256 threads = 8 warps = 2 pixel rows (v, v+1) x 4 sample-chunks.
//   Warp lanes = 32 adjacent u -> adjacent lanes read adjacent x in the
//   transposed volume (coalesced, 4 shared (y,z) rows per warp-sample).
//   Adjacent v rows differ by <0.5 voxel in y -> near-total L1 row reuse.
// ---------------------------------------------------------------------------
__global__ void __launch_bounds__(256) drr_kernel(
    const float* __restrict__ kinv,   // [B,3,3]
    const float* __restrict__ rtinv,  // [B,4,4]
    const float* __restrict__ sdd,    // [B]
    const float* __restrict__ aff,    // [4,4]
    const int*   __restrict__ nsamp,  // scalar
    float* __restrict__ out,          // [B,H,W]
    int uTiles, int vTiles)
{
    const int lane = threadIdx.x & 31;
    const int wrp  = threadIdx.x >> 5;     // 0..7
    const int vsub = wrp >> 2;             // 0..1: which pixel row
    const int wsub = wrp & 3;              // 0..3: which sample chunk
    int bi = blockIdx.x;
    const int ut = bi % uTiles;  bi /= uTiles;
    const int vt = bi % vTiles;
    const int b  = bi / vTiles;
    const int u  = ut * 32 + lane;
    const int v  = vt * 2 + vsub;

    const int   n    = nsamp[0];
    const float invN = 1.0f / (float)(n - 1);

    const float* K  = kinv  + b * 9;
    const float* RT = rtinv + b * 16;
    const float  sd = sdd[b];
    const float  uf = (float)u, vf = (float)v;

    // tgt_cam = K^-1 @ [u,v,1] * sdd
    const float tc0 = fmaf(K[0], uf, fmaf(K[1], vf, K[2])) * sd;
    const float tc1 = fmaf(K[3], uf, fmaf(K[4], vf, K[5])) * sd;
    const float tc2 = fmaf(K[6], uf, fmaf(K[7], vf, K[8])) * sd;

    // ray = R @ tgt_cam  (world space);  src = t
    const float rx = fmaf(RT[0], tc0, fmaf(RT[1],  tc1, RT[2]  * tc2));
    const float ry = fmaf(RT[4], tc0, fmaf(RT[5],  tc1, RT[6]  * tc2));
    const float rz = fmaf(RT[8], tc0, fmaf(RT[9],  tc1, RT[10] * tc2));
    const float sx = RT[3], sy = RT[7], sz = RT[11];

    // Voxel-space line: vox(t) = p0 + t * dd
    const float p0x = aff[0]*sx + aff[1]*sy + aff[2] *sz + aff[3];
    const float p0y = aff[4]*sx + aff[5]*sy + aff[6] *sz + aff[7];
    const float p0z = aff[8]*sx + aff[9]*sy + aff[10]*sz + aff[11];
    const float ddx = aff[0]*rx + aff[1]*ry + aff[2] *rz;
    const float ddy = aff[4]*rx + aff[5]*ry + aff[6] *rz;
    const float ddz = aff[8]*rx + aff[9]*ry + aff[10]*rz;

    // Slab clip: contribution is exactly 0 unless every coordinate is in
    // (-1, VOLD). Conservative by one sample on each side; per-corner bounds
    // checks on the slow path keep boundary samples exact.
    float tmin = 0.0f, tmax = 1.0f;
    {
        const float p0a[3] = {p0x, p0y, p0z};
        const float dda[3] = {ddx, ddy, ddz};
#pragma unroll
        for (int a = 0; a < 3; a++) {
            const float p = p0a[a], d = dda[a];
            if (fabsf(d) > 1e-12f) {
                const float t0 = __fdividef(-1.0f - p, d);
                const float t1 = __fdividef((float)VOLD - p, d);
                tmin = fmaxf(tmin, fminf(t0, t1));
                tmax = fminf(tmax, fmaxf(t0, t1));
            } else if (p <= -1.0f || p >= (float)VOLD) {
                tmin = 1.0f; tmax = 0.0f;
            }
        }
    }

    int s0 = 0, s1 = -1;
    if (tmax >= tmin) {
        s0 = max(0,     (int)floorf(tmin * (float)(n - 1)));
        s1 = min(n - 1, (int)ceilf (tmax * (float)(n - 1)));
    }
    const int total = s1 - s0 + 1;

    float acc = 0.0f;
    if (total > 0 && u < W_ && v < H_) {
        const int chunk = (total + 3) >> 2;        // contiguous chunk per warp
        const int ms = s0 + wsub * chunk;
        const int me = min(s1, ms + chunk - 1);
        for (int si = ms; si <= me; si++) {
            const float t = (float)si * invN;
            const float x = fmaf(t, ddx, p0x);
            const float y = fmaf(t, ddy, p0y);
            const float z = fmaf(t, ddz, p0z);
            const float flx = floorf(x), fly = floorf(y), flz = floorf(z);
            const int ix = (int)flx, iy = (int)fly, iz = (int)flz;
            const float wx = x - flx, wy = y - fly, wz = z - flz;

            float c000, c100, c010, c110, c001, c101, c011, c111;
            if ((unsigned)ix < (VOLD - 1) && (unsigned)iy < (VOLD - 1) &&
                (unsigned)iz < (VOLD - 1)) {
                // Interior fast path: one base address, 8 LDGs with
                // compile-time immediate offsets (x contiguous).
                const float* p = &g_volT[(iz * VOLD + iy) * VOLD + ix];
                c000 = __ldg(p);
                c100 = __ldg(p + 1);
                c010 = __ldg(p + VOLD);
                c110 = __ldg(p + VOLD + 1);
                c001 = __ldg(p + VOLD * VOLD);
                c101 = __ldg(p + VOLD * VOLD + 1);
                c011 = __ldg(p + VOLD * VOLD + VOLD);
                c111 = __ldg(p + VOLD * VOLD + VOLD + 1);
            } else {
                // Boundary slow path: per-corner zero padding.
                c000 = fetchT(ix,     iy,     iz);
                c100 = fetchT(ix + 1, iy,     iz);
                c010 = fetchT(ix,     iy + 1, iz);
                c110 = fetchT(ix + 1, iy + 1, iz);
                c001 = fetchT(ix,     iy,     iz + 1);
                c101 = fetchT(ix + 1, iy,     iz + 1);
                c011 = fetchT(ix,     iy + 1, iz + 1);
                c111 = fetchT(ix + 1, iy + 1, iz + 1);
            }

            const float cx00 = fmaf(wx, c100 - c000, c000);
            const float cx10 = fmaf(wx, c110 - c010, c010);
            const float cx01 = fmaf(wx, c101 - c001, c001);
            const float cx11 = fmaf(wx, c111 - c011, c011);
            const float cy0  = fmaf(wy, cx10 - cx00, cx00);
            const float cy1  = fmaf(wy, cx11 - cx01, cx01);
            acc += fmaf(wz, cy1 - cy0, cy0);
        }
    }

    // Reduce the 4 sample-chunk warps of each pixel row.
    __shared__ float sacc[2][4][32];
    sacc[vsub][wsub][lane] = acc;
    __syncthreads();

    if (wsub == 0 && u < W_ && v < H_) {
        float sum = 0.0f;
#pragma unroll
        for (int j = 0; j < 4; j++) sum += sacc[vsub][j][lane];
        const float step = sqrtf(rx * rx + ry * ry + rz * rz) * invN;
        out[(b * H_ + v) * W_ + u] = sum * step;
    }
}

// ---------------------------------------------------------------------------
// Launch: transpose then DRR, same stream (graph captures the dependency).
// No allocations, no syncs -> graph-capturable.
// ---------------------------------------------------------------------------
extern "C" void kernel_launch(void* const* d_in, const int* in_sizes, int n_in,
                              void* d_out, int out_size) {
    const float* vol   = (const float*)d_in[0];
    const float* kinv  = (const float*)d_in[1];
    const float* rtinv = (const float*)d_in[2];
    const float* sdd   = (const float*)d_in[3];
    const float* aff   = (const float*)d_in[4];
    const int*   nsamp = (const int*)  d_in[5];

    const int B = out_size / (H_ * W_);

    dim3 tgrid(VOLD / 32, VOLD / 32, VOLD);
    transpose_xz<<<tgrid, dim3(32, 8)>>>(vol);

    const int uTiles = (W_ + 31) / 32;
    const int vTiles = (H_ + 1) / 2;
    const int blocks = B * vTiles * uTiles;
    drr_kernel<<<blocks, 256>>>(kinv, rtinv, sdd, aff, nsamp,
                                (float*)d_out, uTiles, vTiles);
}

// round 5
// speedup vs baseline: 1.3136x; 1.3136x over previous
#include <cuda_runtime.h>
#include <math.h>
#include <limits.h>

#define VOLD 256
#define H_ 200
#define W_ 200

// Transposed volume: g_volT[z][y][x], x contiguous. 64 MB static device scratch.
__device__ float g_volT[VOLD * VOLD * VOLD];

// Voxel-space AABB (integer, padded) of everything the rays sample.
__device__ int g_lo[3];   // x,y,z
__device__ int g_hi[3];

// ---------------------------------------------------------------------------
// Shared ray setup: voxel-space line vox(t) = p0 + t*dd for pixel (u,v,b),
// plus slab-clipped sample range [s0,s1]. Used identically by the bounds
// kernel and the DRR kernel so their clip decisions agree.
// ---------------------------------------------------------------------------
struct Ray {
    float p0x, p0y, p0z, ddx, ddy, ddz;
    float rx, ry, rz;
    int s0, s1;       // inclusive sample range; s1 < s0 means empty
};

__device__ __forceinline__ Ray setup_ray(
    const float* __restrict__ kinv, const float* __restrict__ rtinv,
    const float* __restrict__ sdd, const float* __restrict__ aff,
    int b, int u, int v, int n)
{
    Ray r;
    const float* K  = kinv  + b * 9;
    const float* RT = rtinv + b * 16;
    const float  sd = sdd[b];
    const float  uf = (float)u, vf = (float)v;

    const float tc0 = fmaf(K[0], uf, fmaf(K[1], vf, K[2])) * sd;
    const float tc1 = fmaf(K[3], uf, fmaf(K[4], vf, K[5])) * sd;
    const float tc2 = fmaf(K[6], uf, fmaf(K[7], vf, K[8])) * sd;

    r.rx = fmaf(RT[0], tc0, fmaf(RT[1],  tc1, RT[2]  * tc2));
    r.ry = fmaf(RT[4], tc0, fmaf(RT[5],  tc1, RT[6]  * tc2));
    r.rz = fmaf(RT[8], tc0, fmaf(RT[9],  tc1, RT[10] * tc2));
    const float sx = RT[3], sy = RT[7], sz = RT[11];

    r.p0x = aff[0]*sx + aff[1]*sy + aff[2] *sz + aff[3];
    r.p0y = aff[4]*sx + aff[5]*sy + aff[6] *sz + aff[7];
    r.p0z = aff[8]*sx + aff[9]*sy + aff[10]*sz + aff[11];
    r.ddx = aff[0]*r.rx + aff[1]*r.ry + aff[2] *r.rz;
    r.ddy = aff[4]*r.rx + aff[5]*r.ry + aff[6] *r.rz;
    r.ddz = aff[8]*r.rx + aff[9]*r.ry + aff[10]*r.rz;

    // Slab clip: nonzero contribution requires every coordinate in (-1, VOLD).
    float tmin = 0.0f, tmax = 1.0f;
    const float p0a[3] = {r.p0x, r.p0y, r.p0z};
    const float dda[3] = {r.ddx, r.ddy, r.ddz};
#pragma unroll
    for (int a = 0; a < 3; a++) {
        const float p = p0a[a], d = dda[a];
        if (fabsf(d) > 1e-12f) {
            const float t0 = __fdividef(-1.0f - p, d);
            const float t1 = __fdividef((float)VOLD - p, d);
            tmin = fmaxf(tmin, fminf(t0, t1));
            tmax = fminf(tmax, fmaxf(t0, t1));
        } else if (p <= -1.0f || p >= (float)VOLD) {
            tmin = 1.0f; tmax = 0.0f;
        }
    }
    r.s0 = 0; r.s1 = -1;
    if (tmax >= tmin) {
        r.s0 = max(0,     (int)floorf(tmin * (float)(n - 1)));
        r.s1 = min(n - 1, (int)ceilf (tmax * (float)(n - 1)));
    }
    return r;
}

// ---------------------------------------------------------------------------
// Kernel 0a: init bounds (re-run every graph replay for determinism).
// ---------------------------------------------------------------------------
__global__ void init_bounds() {
    if (threadIdx.x < 3) { g_lo[threadIdx.x] = INT_MAX; g_hi[threadIdx.x] = INT_MIN; }
}

// ---------------------------------------------------------------------------
// Kernel 0b: per-ray sampled-endpoint AABB (exact clip math), block-reduced.
// Coordinates along a ray are monotone in t, so the extremes over the sample
// range are at s0 and s1. Pad by 2 voxels each side for floor/corner/fp slack.
// ---------------------------------------------------------------------------
__global__ void __launch_bounds__(256) bounds_kernel(
    const float* __restrict__ kinv, const float* __restrict__ rtinv,
    const float* __restrict__ sdd, const float* __restrict__ aff,
    const int* __restrict__ nsamp, int B)
{
    const int gid = blockIdx.x * blockDim.x + threadIdx.x;
    const int n = nsamp[0];
    const float invN = 1.0f / (float)(n - 1);

    float lmin[3] = {1e30f, 1e30f, 1e30f};
    float lmax[3] = {-1e30f, -1e30f, -1e30f};

    const int total = B * H_ * W_;
    if (gid < total) {
        const int u = gid % W_;
        const int v = (gid / W_) % H_;
        const int b = gid / (W_ * H_);
        Ray r = setup_ray(kinv, rtinv, sdd, aff, b, u, v, n);
        if (r.s1 >= r.s0) {
            const float ta = (float)r.s0 * invN, tb = (float)r.s1 * invN;
            const float xa = fmaf(ta, r.ddx, r.p0x), xb = fmaf(tb, r.ddx, r.p0x);
            const float ya = fmaf(ta, r.ddy, r.p0y), yb = fmaf(tb, r.ddy, r.p0y);
            const float za = fmaf(ta, r.ddz, r.p0z), zb = fmaf(tb, r.ddz, r.p0z);
            lmin[0] = fminf(xa, xb); lmax[0] = fmaxf(xa, xb);
            lmin[1] = fminf(ya, yb); lmax[1] = fmaxf(ya, yb);
            lmin[2] = fminf(za, zb); lmax[2] = fmaxf(za, zb);
        }
    }

    __shared__ float smin[3][256], smax[3][256];
#pragma unroll
    for (int a = 0; a < 3; a++) { smin[a][threadIdx.x] = lmin[a]; smax[a][threadIdx.x] = lmax[a]; }
    __syncthreads();
    for (int s = 128; s > 0; s >>= 1) {
        if (threadIdx.x < s) {
#pragma unroll
            for (int a = 0; a < 3; a++) {
                smin[a][threadIdx.x] = fminf(smin[a][threadIdx.x], smin[a][threadIdx.x + s]);
                smax[a][threadIdx.x] = fmaxf(smax[a][threadIdx.x], smax[a][threadIdx.x + s]);
            }
        }
        __syncthreads();
    }
    if (threadIdx.x < 3) {
        const int a = threadIdx.x;
        if (smin[a][0] < 1e29f) {
            atomicMin(&g_lo[a], max(0,        (int)floorf(smin[a][0]) - 2));
            atomicMax(&g_hi[a], min(VOLD - 1, (int)floorf(smax[a][0]) + 3));
        }
    }
}

// ---------------------------------------------------------------------------
// Kernel 1: x<->z transpose, restricted to the sampled AABB (tile early-exit).
// ---------------------------------------------------------------------------
__global__ void __launch_bounds__(256) transpose_xz(const float* __restrict__ vol) {
    const int xB = blockIdx.x * 32;
    const int zB = blockIdx.y * 32;
    const int y  = blockIdx.z;

    // Load bounds once, then skip tiles fully outside the sampled AABB.
    const int lx = g_lo[0], ly = g_lo[1], lz = g_lo[2];
    const int hx = g_hi[0], hy = g_hi[1], hz = g_hi[2];
    if (y < ly || y > hy) return;
    if (xB + 31 < lx || xB > hx) return;
    if (zB + 31 < lz || zB > hz) return;

    __shared__ float tile[32][33];
    const int tx = threadIdx.x;           // 0..31
    const int ty = threadIdx.y;           // 0..7

    // Read: vol[x][y][z], z contiguous -> lanes sweep z (coalesced)
#pragma unroll
    for (int i = 0; i < 32; i += 8) {
        tile[ty + i][tx] = vol[((xB + ty + i) * VOLD + y) * VOLD + (zB + tx)];
    }
    __syncthreads();
    // Write: g_volT[z][y][x], x contiguous -> lanes sweep x (coalesced)
#pragma unroll
    for (int i = 0; i < 32; i += 8) {
        g_volT[((zB + ty + i) * VOLD + y) * VOLD + (xB + tx)] = tile[tx][ty + i];
    }
}

// Trilinear corner fetch with zero padding (map_coordinates mode='constant').
__device__ __forceinline__ float fetchT(int x, int y, int z) {
    if ((unsigned)x < (unsigned)VOLD && (unsigned)y < (unsigned)VOLD &&
        (unsigned)z < (unsigned)VOLD) {
        return __ldg(&g_volT[(z * VOLD + y) * VOLD + x]);
    }
    return 0.0f;
}

// ---------------------------------------------------------------------------
// Kernel 2: DRR ray marching.
//   block = 256 threads = 8 warps = 1 pixel row x 8 sample-chunks
//   (grid = B*H*uTiles = 1400 -> ~95% occupancy; Round-2's 2-rows/block
//   halved the grid and capped occupancy at 58%).
//   Warp lanes = 32 adjacent u -> adjacent lanes read adjacent x in the
//   transposed volume. Inner loop unrolled 2x for 16 outstanding LDGs.
// ---------------------------------------------------------------------------
__global__ void __launch_bounds__(256) drr_kernel(
    const float* __restrict__ kinv, const float* __restrict__ rtinv,
    const float* __restrict__ sdd, const float* __restrict__ aff,
    const int* __restrict__ nsamp,
    float* __restrict__ out, int uTiles)
{
    const int lane = threadIdx.x & 31;
    const int wrp  = threadIdx.x >> 5;     // 0..7 sample chunk
    int bi = blockIdx.x;
    const int ut = bi % uTiles;  bi /= uTiles;
    const int v  = bi % H_;
    const int b  = bi / H_;
    const int u  = ut * 32 + lane;

    const int   n    = nsamp[0];
    const float invN = 1.0f / (float)(n - 1);

    const Ray r = setup_ray(kinv, rtinv, sdd, aff, b, min(u, W_ - 1), v, n);
    const int total = r.s1 - r.s0 + 1;

    float acc = 0.0f;
    if (total > 0 && u < W_) {
        const int chunk = (total + 7) >> 3;
        const int ms = r.s0 + wrp * chunk;
        const int me = min(r.s1, ms + chunk - 1);
#pragma unroll 2
        for (int si = ms; si <= me; si++) {
            const float t = (float)si * invN;
            const float x = fmaf(t, r.ddx, r.p0x);
            const float y = fmaf(t, r.ddy, r.p0y);
            const float z = fmaf(t, r.ddz, r.p0z);
            const float flx = floorf(x), fly = floorf(y), flz = floorf(z);
            const int ix = (int)flx, iy = (int)fly, iz = (int)flz;
            const float wx = x - flx, wy = y - fly, wz = z - flz;

            float c000, c100, c010, c110, c001, c101, c011, c111;
            if ((unsigned)ix < (VOLD - 1) && (unsigned)iy < (VOLD - 1) &&
                (unsigned)iz < (VOLD - 1)) {
                // Interior fast path: one base, 8 LDGs with immediate offsets.
                const float* p = &g_volT[(iz * VOLD + iy) * VOLD + ix];
                c000 = __ldg(p);
                c100 = __ldg(p + 1);
                c010 = __ldg(p + VOLD);
                c110 = __ldg(p + VOLD + 1);
                c001 = __ldg(p + VOLD * VOLD);
                c101 = __ldg(p + VOLD * VOLD + 1);
                c011 = __ldg(p + VOLD * VOLD + VOLD);
                c111 = __ldg(p + VOLD * VOLD + VOLD + 1);
            } else {
                c000 = fetchT(ix,     iy,     iz);
                c100 = fetchT(ix + 1, iy,     iz);
                c010 = fetchT(ix,     iy + 1, iz);
                c110 = fetchT(ix + 1, iy + 1, iz);
                c001 = fetchT(ix,     iy,     iz + 1);
                c101 = fetchT(ix + 1, iy,     iz + 1);
                c011 = fetchT(ix,     iy + 1, iz + 1);
                c111 = fetchT(ix + 1, iy + 1, iz + 1);
            }

            const float cx00 = fmaf(wx, c100 - c000, c000);
            const float cx10 = fmaf(wx, c110 - c010, c010);
            const float cx01 = fmaf(wx, c101 - c001, c001);
            const float cx11 = fmaf(wx, c111 - c011, c011);
            const float cy0  = fmaf(wy, cx10 - cx00, cx00);
            const float cy1  = fmaf(wy, cx11 - cx01, cx01);
            acc += fmaf(wz, cy1 - cy0, cy0);
        }
    }

    __shared__ float sacc[8][32];
    sacc[wrp][lane] = acc;
    __syncthreads();

    if (wrp == 0 && u < W_) {
        float sum = 0.0f;
#pragma unroll
        for (int j = 0; j < 8; j++) sum += sacc[j][lane];
        const float step = sqrtf(r.rx*r.rx + r.ry*r.ry + r.rz*r.rz) * invN;
        out[(b * H_ + v) * W_ + u] = sum * step;
    }
}

// ---------------------------------------------------------------------------
// Launch: init -> bounds -> transpose(AABB only) -> DRR. Same stream; the
// graph captures the dependency chain. No allocations, no syncs.
// ---------------------------------------------------------------------------
extern "C" void kernel_launch(void* const* d_in, const int* in_sizes, int n_in,
                              void* d_out, int out_size) {
    const float* vol   = (const float*)d_in[0];
    const float* kinv  = (const float*)d_in[1];
    const float* rtinv = (const float*)d_in[2];
    const float* sdd   = (const float*)d_in[3];
    const float* aff   = (const float*)d_in[4];
    const int*   nsamp = (const int*)  d_in[5];

    const int B = out_size / (H_ * W_);

    init_bounds<<<1, 32>>>();
    const int nrays = B * H_ * W_;
    bounds_kernel<<<(nrays + 255) / 256, 256>>>(kinv, rtinv, sdd, aff, nsamp, B);

    dim3 tgrid(VOLD / 32, VOLD / 32, VOLD);
    transpose_xz<<<tgrid, dim3(32, 8)>>>(vol);

    const int uTiles = (W_ + 31) / 32;
    const int blocks = B * H_ * uTiles;
    drr_kernel<<<blocks, 256>>>(kinv, rtinv, sdd, aff, nsamp,
                                (float*)d_out, uTiles);
}